// round 2
// baseline (speedup 1.0000x reference)
#include <cuda_runtime.h>
#include <cstdint>

#define NN   32
#define CC   64
#define HH   112
#define WW   112
#define HW   (HH*WW)        // 12544
#define OO   64
#define TAPS 9

// Static device scratch (no allocation)
__device__ __align__(16) unsigned long long g_packed[NN * HW];  // bit c = (A[n][c][y][x] > 0)
__device__ unsigned long long g_wbits[OO * TAPS];               // bit c = (W[o][c][tap] > 0)
__device__ int                g_fix[16 * OO];                   // per edge-class per o correction

// ---------------------------------------------------------------------------
// Kernel 1: pack weights. One warp per (o,t); lane covers channels lane, lane+32.
// weights layout: [(o*64+c)*9 + t]
// ---------------------------------------------------------------------------
__global__ void pack_weights_kernel(const float* __restrict__ w) {
    int wid  = blockIdx.x * (blockDim.x >> 5) + (threadIdx.x >> 5);
    int lane = threadIdx.x & 31;
    if (wid >= OO * TAPS) return;
    int o = wid / TAPS, t = wid % TAPS;
    float v0 = w[(o * CC + lane) * TAPS + t];
    float v1 = w[(o * CC + lane + 32) * TAPS + t];
    unsigned b0 = __ballot_sync(0xFFFFFFFFu, v0 > 0.0f);
    unsigned b1 = __ballot_sync(0xFFFFFFFFu, v1 > 0.0f);
    if (lane == 0)
        g_wbits[wid] = (unsigned long long)b0 | ((unsigned long long)b1 << 32);
}

// ---------------------------------------------------------------------------
// Kernel 1b: precompute border fix table. blockIdx.x = edge class mask m
// (bit0=T, bit1=B, bit2=L, bit3=R), threadIdx.x = o.
// fix = 2*sum_{invalid taps} popc(w) - 64*n_missing
// ---------------------------------------------------------------------------
__global__ void pack_fix_kernel() {
    int m = blockIdx.x;     // 0..15
    int o = threadIdx.x;    // 0..63
    bool T = m & 1, B = m & 2, L = m & 4, R = m & 8;
    int corr = 0, nmiss = 0;
#pragma unroll
    for (int t = 0; t < 9; t++) {
        int r = t / 3, c = t % 3;
        bool inv = (T && r == 0) || (B && r == 2) || (L && c == 0) || (R && c == 2);
        if (inv) {
            corr += __popcll(g_wbits[o * TAPS + t]);
            nmiss++;
        }
    }
    g_fix[m * OO + o] = 2 * corr - CC * nmiss;
}

// ---------------------------------------------------------------------------
// Kernel 2: pack activations. Each thread packs 4 consecutive pixels using
// float4 loads per channel. HW divisible by 4; warps never cross n boundary.
// ---------------------------------------------------------------------------
__global__ void pack_act_kernel(const float* __restrict__ act) {
    int tidg = blockIdx.x * blockDim.x + threadIdx.x;
    int p0   = tidg * 4;                  // global packed index base
    int n    = p0 / HW;
    int p    = p0 - n * HW;

    const float* base = act + (long)(n * CC) * HW + p;
    unsigned long long w0 = 0, w1 = 0, w2 = 0, w3 = 0;
#pragma unroll
    for (int c = 0; c < CC; c++) {
        float4 v = *(const float4*)(base + (long)c * HW);
        w0 |= (unsigned long long)(v.x > 0.0f) << c;
        w1 |= (unsigned long long)(v.y > 0.0f) << c;
        w2 |= (unsigned long long)(v.z > 0.0f) << c;
        w3 |= (unsigned long long)(v.w > 0.0f) << c;
    }
    ulonglong2* dst = (ulonglong2*)(g_packed + p0);
    dst[0] = make_ulonglong2(w0, w1);
    dst[1] = make_ulonglong2(w2, w3);
}

// ---------------------------------------------------------------------------
// Kernel 3: binary conv, branch-free interior formula everywhere.
// Each thread: 4 pixels (x0..x0+3), window 3 rows x 6 packed words.
// res = 576 - 2 * sum_taps popc(a ^ w);  OOB words are 0 (fixed later).
// Block (28,8) = 224 threads; grid (14, 32).
// ---------------------------------------------------------------------------
__global__ __launch_bounds__(224)
void bconv_kernel(float* __restrict__ out) {
    __shared__ unsigned long long ws[OO * TAPS];

    int t = threadIdx.y * 28 + threadIdx.x;
    for (int i = t; i < OO * TAPS; i += 224)
        ws[i] = g_wbits[i];
    __syncthreads();

    int x0 = threadIdx.x * 4;
    int y  = blockIdx.x * 8 + threadIdx.y;
    int n  = blockIdx.y;

    const unsigned long long* pb = g_packed + (long)n * HW;

    // 3x6 window, zero for OOB
    unsigned long long a[3][6];
#pragma unroll
    for (int r = 0; r < 3; r++) {
        int yy = y - 1 + r;
        bool rv = (unsigned)yy < (unsigned)HH;
        const unsigned long long* row = pb + yy * WW;
#pragma unroll
        for (int c = 0; c < 6; c++) {
            int xx = x0 - 1 + c;
            bool v = rv && ((unsigned)xx < (unsigned)WW);
            a[r][c] = v ? row[xx] : 0ull;
        }
    }

    float* ob = out + ((long)(n * OO)) * HW + y * WW + x0;

#pragma unroll 2
    for (int o = 0; o < OO; o++) {
        const unsigned long long* wr = ws + o * TAPS;
        int acc0 = 0, acc1 = 0, acc2 = 0, acc3 = 0;
#pragma unroll
        for (int r = 0; r < 3; r++) {
#pragma unroll
            for (int j = 0; j < 3; j++) {
                unsigned long long wv = wr[r * 3 + j];
                acc0 += __popcll(a[r][j]     ^ wv);
                acc1 += __popcll(a[r][j + 1] ^ wv);
                acc2 += __popcll(a[r][j + 2] ^ wv);
                acc3 += __popcll(a[r][j + 3] ^ wv);
            }
        }
        float4 res;
        res.x = (float)(CC * TAPS - 2 * acc0);
        res.y = (float)(CC * TAPS - 2 * acc1);
        res.z = (float)(CC * TAPS - 2 * acc2);
        res.w = (float)(CC * TAPS - 2 * acc3);
        *(float4*)(ob + (long)o * HW) = res;
    }
}

// ---------------------------------------------------------------------------
// Kernel 4: border fix. 444 border pixels per image; one thread per pixel,
// loops all 64 o. grid = NN, block = 448 (444 active).
// ---------------------------------------------------------------------------
__global__ void fix_border_kernel(float* __restrict__ out) {
    int i = threadIdx.x;
    if (i >= 444) return;
    int n = blockIdx.x;

    int y, x;
    if (i < 112)       { y = 0;        x = i; }
    else if (i < 224)  { y = 111;      x = i - 112; }
    else if (i < 334)  { y = i - 223;  x = 0; }      // y = 1..110
    else               { y = i - 333;  x = 111; }    // y = 1..110

    int m = (y == 0 ? 1 : 0) | (y == 111 ? 2 : 0) | (x == 0 ? 4 : 0) | (x == 111 ? 8 : 0);
    const int* fx = g_fix + m * OO;

    float* ob = out + ((long)(n * OO)) * HW + y * WW + x;
#pragma unroll 4
    for (int o = 0; o < OO; o++) {
        ob[(long)o * HW] += (float)fx[o];
    }
}

// ---------------------------------------------------------------------------
extern "C" void kernel_launch(void* const* d_in, const int* in_sizes, int n_in,
                              void* d_out, int out_size) {
    const float* act = (const float*)d_in[0];   // [32,64,112,112]
    const float* w   = (const float*)d_in[1];   // [64*64*9, 1]
    float* out       = (float*)d_out;           // [32,64,112,112]

    // 576 warps for weight pack: 72 blocks x 256 threads
    pack_weights_kernel<<<72, 256>>>(w);
    pack_fix_kernel<<<16, OO>>>();

    // 32*12544/4 = 100352 threads
    pack_act_kernel<<<(NN * HW / 4) / 256, 256>>>(act);

    dim3 block(28, 8);
    dim3 grid(HH / 8, NN);
    bconv_kernel<<<grid, block>>>(out);

    fix_border_kernel<<<NN, 448>>>(out);
}

// round 4
// speedup vs baseline: 1.0600x; 1.0600x over previous
#include <cuda_runtime.h>
#include <cstdint>

#define NN   32
#define CC   64
#define HH   112
#define WW   112
#define HW   (HH*WW)        // 12544
#define OO   64
#define TAPS 9
#define OB   32             // output channels per block (o-split)

// Static device scratch (no allocation)
__device__ __align__(16) unsigned long long g_packed[NN * HW];  // bit c = (A[n][c][y][x] > 0)
__device__ unsigned long long g_wbits[OO * TAPS];               // bit c = (W[o][c][tap] > 0)
__device__ int                g_fix[16 * OO];                   // per edge-class per o correction

// ---------------------------------------------------------------------------
// Kernel 1: pack weights. One warp per (o,t); lane covers channels lane, lane+32.
// ---------------------------------------------------------------------------
__global__ void pack_weights_kernel(const float* __restrict__ w) {
    int wid  = blockIdx.x * (blockDim.x >> 5) + (threadIdx.x >> 5);
    int lane = threadIdx.x & 31;
    if (wid >= OO * TAPS) return;
    int o = wid / TAPS, t = wid % TAPS;
    float v0 = w[(o * CC + lane) * TAPS + t];
    float v1 = w[(o * CC + lane + 32) * TAPS + t];
    unsigned b0 = __ballot_sync(0xFFFFFFFFu, v0 > 0.0f);
    unsigned b1 = __ballot_sync(0xFFFFFFFFu, v1 > 0.0f);
    if (lane == 0)
        g_wbits[wid] = (unsigned long long)b0 | ((unsigned long long)b1 << 32);
}

// ---------------------------------------------------------------------------
// Kernel 1b: border fix table. blockIdx.x = edge class mask m
// (bit0=T, bit1=B, bit2=L, bit3=R), threadIdx.x = o.
// fix = 2*sum_{invalid taps} popc(w) - 64*n_missing
// ---------------------------------------------------------------------------
__global__ void pack_fix_kernel() {
    int m = blockIdx.x;     // 0..15
    int o = threadIdx.x;    // 0..63
    bool T = m & 1, B = m & 2, L = m & 4, R = m & 8;
    int corr = 0, nmiss = 0;
#pragma unroll
    for (int t = 0; t < 9; t++) {
        int r = t / 3, c = t % 3;
        bool inv = (T && r == 0) || (B && r == 2) || (L && c == 0) || (R && c == 2);
        if (inv) {
            corr += __popcll(g_wbits[o * TAPS + t]);
            nmiss++;
        }
    }
    g_fix[m * OO + o] = 2 * corr - CC * nmiss;
}

// ---------------------------------------------------------------------------
// Kernel 2: pack activations. Each thread packs 4 consecutive pixels via
// float4 loads per channel.
// ---------------------------------------------------------------------------
__global__ void pack_act_kernel(const float* __restrict__ act) {
    int tidg = blockIdx.x * blockDim.x + threadIdx.x;
    int p0   = tidg * 4;
    int n    = p0 / HW;
    int p    = p0 - n * HW;

    const float* base = act + (long)(n * CC) * HW + p;
    unsigned long long w0 = 0, w1 = 0, w2 = 0, w3 = 0;
#pragma unroll
    for (int c = 0; c < CC; c++) {
        float4 v = *(const float4*)(base + (long)c * HW);
        w0 |= (unsigned long long)(v.x > 0.0f) << c;
        w1 |= (unsigned long long)(v.y > 0.0f) << c;
        w2 |= (unsigned long long)(v.z > 0.0f) << c;
        w3 |= (unsigned long long)(v.w > 0.0f) << c;
    }
    ulonglong2* dst = (ulonglong2*)(g_packed + p0);
    dst[0] = make_ulonglong2(w0, w1);
    dst[1] = make_ulonglong2(w2, w3);
}

// ---------------------------------------------------------------------------
// Kernel 3: binary conv, branch-free interior formula everywhere.
// Thread: 4 pixels, window 3x6 words in regs. Block (28,8)=224, 32 o's/block.
// grid (14, 32, 2): x = row-group, y = n, z = o-half.
// res = 576 - 2*acc via magic-number trick (no I2F):
//   as_float(0x4B000000 | acc) = 8388608 + acc   (acc < 2^23)
//   res = fmaf(-2, 8388608+acc, 16777792) = 576 - 2*acc   [2^24 + 576]
// ---------------------------------------------------------------------------
__global__ __launch_bounds__(224)
void bconv_kernel(float* __restrict__ out) {
    __shared__ unsigned long long ws[OB * TAPS];

    int obase = blockIdx.z * OB;
    int t = threadIdx.y * 28 + threadIdx.x;
    if (t < OB * TAPS) ws[t] = g_wbits[obase * TAPS + t];
    if (t + 224 < OB * TAPS) ws[t + 224] = g_wbits[obase * TAPS + t + 224];
    __syncthreads();

    int x0 = threadIdx.x * 4;
    int y  = blockIdx.x * 8 + threadIdx.y;
    int n  = blockIdx.y;

    const unsigned long long* pb = g_packed + (long)n * HW;

    // 3x6 window, zero for OOB (fixed by border kernel)
    unsigned long long a[3][6];
#pragma unroll
    for (int r = 0; r < 3; r++) {
        int yy = y - 1 + r;
        bool rv = (unsigned)yy < (unsigned)HH;
        const unsigned long long* row = pb + yy * WW;
#pragma unroll
        for (int c = 0; c < 6; c++) {
            int xx = x0 - 1 + c;
            bool v = rv && ((unsigned)xx < (unsigned)WW);
            a[r][c] = v ? row[xx] : 0ull;
        }
    }

    const float MAGIC_SUB = 16777792.0f;  // 2^24 + 576  (FIXED)

    float* ob = out + ((long)(n * OO + obase)) * HW + y * WW + x0;

#pragma unroll 2
    for (int o = 0; o < OB; o++) {
        const unsigned long long* wr = ws + o * TAPS;
        int acc0 = 0, acc1 = 0, acc2 = 0, acc3 = 0;
#pragma unroll
        for (int r = 0; r < 3; r++) {
#pragma unroll
            for (int j = 0; j < 3; j++) {
                unsigned long long wv = wr[r * 3 + j];
                acc0 += __popcll(a[r][j]     ^ wv);
                acc1 += __popcll(a[r][j + 1] ^ wv);
                acc2 += __popcll(a[r][j + 2] ^ wv);
                acc3 += __popcll(a[r][j + 3] ^ wv);
            }
        }
        float4 res;
        res.x = fmaf(-2.0f, __int_as_float(0x4B000000 | acc0), MAGIC_SUB);
        res.y = fmaf(-2.0f, __int_as_float(0x4B000000 | acc1), MAGIC_SUB);
        res.z = fmaf(-2.0f, __int_as_float(0x4B000000 | acc2), MAGIC_SUB);
        res.w = fmaf(-2.0f, __int_as_float(0x4B000000 | acc3), MAGIC_SUB);
        *(float4*)(ob + (long)o * HW) = res;
    }
}

// ---------------------------------------------------------------------------
// Kernel 4: border fix. 444 border pixels per image; one thread per pixel.
// ---------------------------------------------------------------------------
__global__ void fix_border_kernel(float* __restrict__ out) {
    int i = threadIdx.x;
    if (i >= 444) return;
    int n = blockIdx.x;

    int y, x;
    if (i < 112)       { y = 0;        x = i; }
    else if (i < 224)  { y = 111;      x = i - 112; }
    else if (i < 334)  { y = i - 223;  x = 0; }      // y = 1..110
    else               { y = i - 333;  x = 111; }    // y = 1..110

    int m = (y == 0 ? 1 : 0) | (y == 111 ? 2 : 0) | (x == 0 ? 4 : 0) | (x == 111 ? 8 : 0);
    const int* fx = g_fix + m * OO;

    float* ob = out + ((long)(n * OO)) * HW + y * WW + x;
#pragma unroll 4
    for (int o = 0; o < OO; o++) {
        ob[(long)o * HW] += (float)fx[o];
    }
}

// ---------------------------------------------------------------------------
extern "C" void kernel_launch(void* const* d_in, const int* in_sizes, int n_in,
                              void* d_out, int out_size) {
    const float* act = (const float*)d_in[0];   // [32,64,112,112]
    const float* w   = (const float*)d_in[1];   // [64*64*9, 1]
    float* out       = (float*)d_out;           // [32,64,112,112]

    pack_weights_kernel<<<72, 256>>>(w);
    pack_fix_kernel<<<16, OO>>>();

    pack_act_kernel<<<(NN * HW / 4) / 256, 256>>>(act);

    dim3 block(28, 8);
    dim3 grid(HH / 8, NN, 2);
    bconv_kernel<<<grid, block>>>(out);

    fix_border_kernel<<<NN, 448>>>(out);
}

// round 5
// speedup vs baseline: 1.2256x; 1.1562x over previous
#include <cuda_runtime.h>
#include <cstdint>

#define NN   32
#define CC   64
#define HH   112
#define WW   112
#define HW   (HH*WW)        // 12544
#define OO   64
#define TAPS 9
#define WSTRIDE 10          // padded weight row (16B-aligned rows: 80 bytes)
#define OB   32             // output channels per block (o-split)

typedef unsigned long long u64;

// Static device scratch (no allocation)
__device__ __align__(16) u64 g_packed[NN * HW];        // bit c = (A[n][c][y][x] > 0)
__device__ __align__(16) u64 g_wbits[OO * WSTRIDE];    // padded rows of 10
__device__ int               g_fix[16 * OO];           // per edge-class per o correction

// Full adder (carry-save): compiles to 2 LOP3 per 32-bit half.
__device__ __forceinline__ void csa(u64& s, u64& c, u64 x, u64 y, u64 z) {
    u64 u = x ^ y;
    s = u ^ z;
    c = (x & y) | (u & z);
}

// ---------------------------------------------------------------------------
// Kernel 1: pack weights. One warp per (o,t); lane covers channels lane, lane+32.
// ---------------------------------------------------------------------------
__global__ void pack_weights_kernel(const float* __restrict__ w) {
    int wid  = blockIdx.x * (blockDim.x >> 5) + (threadIdx.x >> 5);
    int lane = threadIdx.x & 31;
    if (wid >= OO * TAPS) return;
    int o = wid / TAPS, t = wid % TAPS;
    float v0 = w[(o * CC + lane) * TAPS + t];
    float v1 = w[(o * CC + lane + 32) * TAPS + t];
    unsigned b0 = __ballot_sync(0xFFFFFFFFu, v0 > 0.0f);
    unsigned b1 = __ballot_sync(0xFFFFFFFFu, v1 > 0.0f);
    if (lane == 0)
        g_wbits[o * WSTRIDE + t] = (u64)b0 | ((u64)b1 << 32);
}

// ---------------------------------------------------------------------------
// Kernel 1b: border fix table. blockIdx.x = edge class mask m, threadIdx.x = o.
// fix = 2*sum_{invalid taps} popc(w) - 64*n_missing
// ---------------------------------------------------------------------------
__global__ void pack_fix_kernel() {
    int m = blockIdx.x;     // 0..15
    int o = threadIdx.x;    // 0..63
    bool T = m & 1, B = m & 2, L = m & 4, R = m & 8;
    int corr = 0, nmiss = 0;
#pragma unroll
    for (int t = 0; t < 9; t++) {
        int r = t / 3, c = t % 3;
        bool inv = (T && r == 0) || (B && r == 2) || (L && c == 0) || (R && c == 2);
        if (inv) {
            corr += __popcll(g_wbits[o * WSTRIDE + t]);
            nmiss++;
        }
    }
    g_fix[m * OO + o] = 2 * corr - CC * nmiss;
}

// ---------------------------------------------------------------------------
// Kernel 2: pack activations. Each thread packs 4 consecutive pixels via
// float4 loads per channel.
// ---------------------------------------------------------------------------
__global__ void pack_act_kernel(const float* __restrict__ act) {
    int tidg = blockIdx.x * blockDim.x + threadIdx.x;
    int p0   = tidg * 4;
    int n    = p0 / HW;
    int p    = p0 - n * HW;

    const float* base = act + (long)(n * CC) * HW + p;
    u64 w0 = 0, w1 = 0, w2 = 0, w3 = 0;
#pragma unroll
    for (int c = 0; c < CC; c++) {
        float4 v = *(const float4*)(base + (long)c * HW);
        w0 |= (u64)(v.x > 0.0f) << c;
        w1 |= (u64)(v.y > 0.0f) << c;
        w2 |= (u64)(v.z > 0.0f) << c;
        w3 |= (u64)(v.w > 0.0f) << c;
    }
    ulonglong2* dst = (ulonglong2*)(g_packed + p0);
    dst[0] = make_ulonglong2(w0, w1);
    dst[1] = make_ulonglong2(w2, w3);
}

// ---------------------------------------------------------------------------
// Kernel 3: binary conv with CSA-compressed popcount.
// Thread: 4 pixels, window 3x6 words. Block (28,4)=112; grid (28,32,2).
// Per (o,px): 9 xors -> CSA tree -> 5 popcll instead of 9.
// res = 576 - 2*acc via magic fma:
//   as_float(0x4B000000|acc) = 2^23 + acc;  fmaf(-2, ., 2^24+576) = 576-2acc
// ---------------------------------------------------------------------------
__global__ __launch_bounds__(112)
void bconv_kernel(float* __restrict__ out) {
    __shared__ __align__(16) u64 ws[OB * WSTRIDE];

    int obase = blockIdx.z * OB;
    int t = threadIdx.y * 28 + threadIdx.x;
    for (int i = t; i < OB * WSTRIDE; i += 112)
        ws[i] = g_wbits[obase * WSTRIDE + i];
    __syncthreads();

    int x0 = threadIdx.x * 4;
    int y  = blockIdx.x * 4 + threadIdx.y;
    int n  = blockIdx.y;

    const u64* pb = g_packed + (long)n * HW;

    // 3x6 window, zero for OOB (fixed by border kernel)
    u64 a[3][6];
#pragma unroll
    for (int r = 0; r < 3; r++) {
        int yy = y - 1 + r;
        bool rv = (unsigned)yy < (unsigned)HH;
        const u64* row = pb + yy * WW;
#pragma unroll
        for (int c = 0; c < 6; c++) {
            int xx = x0 - 1 + c;
            bool v = rv && ((unsigned)xx < (unsigned)WW);
            a[r][c] = v ? row[xx] : 0ull;
        }
    }

    const float MAGIC_SUB = 16777792.0f;  // 2^24 + 576

    float* ob = out + ((long)(n * OO + obase)) * HW + y * WW + x0;

#pragma unroll 2
    for (int o = 0; o < OB; o++) {
        // Load 9 weight words: 2x LDS.128 + 1x LDS.64 (rows are 16B-aligned)
        const ulonglong2* wr2 = (const ulonglong2*)(ws + o * WSTRIDE);
        ulonglong2 wp0 = wr2[0], wp1 = wr2[1], wp2 = wr2[2], wp3 = wr2[3];
        u64 wv[9] = { wp0.x, wp0.y, wp1.x, wp1.y, wp2.x, wp2.y, wp3.x, wp3.y,
                      ws[o * WSTRIDE + 8] };

        float4 res;
#pragma unroll
        for (int px = 0; px < 4; px++) {
            u64 x0_, x1_, x2_, s0, s1, s2, s3, c0, c1, c2, c3;
            // row 0
            x0_ = a[0][px]     ^ wv[0];
            x1_ = a[0][px + 1] ^ wv[1];
            x2_ = a[0][px + 2] ^ wv[2];
            csa(s0, c0, x0_, x1_, x2_);
            // row 1
            x0_ = a[1][px]     ^ wv[3];
            x1_ = a[1][px + 1] ^ wv[4];
            x2_ = a[1][px + 2] ^ wv[5];
            csa(s1, c1, x0_, x1_, x2_);
            // row 2
            x0_ = a[2][px]     ^ wv[6];
            x1_ = a[2][px + 1] ^ wv[7];
            x2_ = a[2][px + 2] ^ wv[8];
            csa(s2, c2, x0_, x1_, x2_);
            // compress carries
            csa(s3, c3, c0, c1, c2);

            int acc = __popcll(s0) + __popcll(s1) + __popcll(s2)
                    + 2 * __popcll(s3) + 4 * __popcll(c3);
            float v = fmaf(-2.0f, __int_as_float(0x4B000000 | acc), MAGIC_SUB);
            if (px == 0) res.x = v;
            else if (px == 1) res.y = v;
            else if (px == 2) res.z = v;
            else res.w = v;
        }
        *(float4*)(ob + (long)o * HW) = res;
    }
}

// ---------------------------------------------------------------------------
// Kernel 4: border fix. 444 border pixels per image; one thread per pixel.
// ---------------------------------------------------------------------------
__global__ void fix_border_kernel(float* __restrict__ out) {
    int i = threadIdx.x;
    if (i >= 444) return;
    int n = blockIdx.x;

    int y, x;
    if (i < 112)       { y = 0;        x = i; }
    else if (i < 224)  { y = 111;      x = i - 112; }
    else if (i < 334)  { y = i - 223;  x = 0; }      // y = 1..110
    else               { y = i - 333;  x = 111; }    // y = 1..110

    int m = (y == 0 ? 1 : 0) | (y == 111 ? 2 : 0) | (x == 0 ? 4 : 0) | (x == 111 ? 8 : 0);
    const int* fx = g_fix + m * OO;

    float* ob = out + ((long)(n * OO)) * HW + y * WW + x;
#pragma unroll 4
    for (int o = 0; o < OO; o++) {
        ob[(long)o * HW] += (float)fx[o];
    }
}

// ---------------------------------------------------------------------------
extern "C" void kernel_launch(void* const* d_in, const int* in_sizes, int n_in,
                              void* d_out, int out_size) {
    const float* act = (const float*)d_in[0];   // [32,64,112,112]
    const float* w   = (const float*)d_in[1];   // [64*64*9, 1]
    float* out       = (float*)d_out;           // [32,64,112,112]

    pack_weights_kernel<<<72, 256>>>(w);
    pack_fix_kernel<<<16, OO>>>();

    pack_act_kernel<<<(NN * HW / 4) / 128, 128>>>(act);

    dim3 block(28, 4);
    dim3 grid(HH / 4, NN, 2);
    bconv_kernel<<<grid, block>>>(out);

    fix_border_kernel<<<NN, 448>>>(out);
}

// round 6
// speedup vs baseline: 1.3749x; 1.1218x over previous
#include <cuda_runtime.h>
#include <cstdint>

#define NN   32
#define CC   64
#define HH   112
#define WW   112
#define HW   (HH*WW)        // 12544
#define OO   64
#define TAPS 9
#define WSTRIDE 10          // padded weight row (16B-aligned rows: 80 bytes)
#define OB   32             // output channels per block (o-split)

typedef unsigned long long u64;

// Static device scratch (no allocation)
__device__ __align__(16) u64 g_packed[NN * HW];        // bit c = (A[n][c][y][x] > 0)
__device__ __align__(16) u64 g_wbits[OO * WSTRIDE];    // padded rows of 10
__device__ float             g_fixf[16 * OO];          // per edge-class per o correction (float)

// Full adder (carry-save): s = XOR3 (1 LOP3/32), c = MAJ3 (1 LOP3/32).
__device__ __forceinline__ void csa(u64& s, u64& c, u64 x, u64 y, u64 z) {
    u64 u = x ^ y;
    s = u ^ z;
    c = (x & y) | (u & z);
}

// ---------------------------------------------------------------------------
// Kernel 1: pack weights. One warp per (o,t); lane covers channels lane, lane+32.
// ---------------------------------------------------------------------------
__global__ void pack_weights_kernel(const float* __restrict__ w) {
    int wid  = blockIdx.x * (blockDim.x >> 5) + (threadIdx.x >> 5);
    int lane = threadIdx.x & 31;
    if (wid >= OO * TAPS) return;
    int o = wid / TAPS, t = wid % TAPS;
    float v0 = w[(o * CC + lane) * TAPS + t];
    float v1 = w[(o * CC + lane + 32) * TAPS + t];
    unsigned b0 = __ballot_sync(0xFFFFFFFFu, v0 > 0.0f);
    unsigned b1 = __ballot_sync(0xFFFFFFFFu, v1 > 0.0f);
    if (lane == 0)
        g_wbits[o * WSTRIDE + t] = (u64)b0 | ((u64)b1 << 32);
}

// ---------------------------------------------------------------------------
// Kernel 1b: border fix table (float). blockIdx.x = edge class mask m
// (bit0: y==0, bit1: y==111, bit2: x==0, bit3: x==111), threadIdx.x = o.
// fix = 2*sum_{invalid taps} popc(w) - 64*n_missing ;  class 0 -> 0.0f
// ---------------------------------------------------------------------------
__global__ void pack_fix_kernel() {
    int m = blockIdx.x;     // 0..15
    int o = threadIdx.x;    // 0..63
    bool T = m & 1, B = m & 2, L = m & 4, R = m & 8;
    int corr = 0, nmiss = 0;
#pragma unroll
    for (int t = 0; t < 9; t++) {
        int r = t / 3, c = t % 3;
        bool inv = (T && r == 0) || (B && r == 2) || (L && c == 0) || (R && c == 2);
        if (inv) {
            corr += __popcll(g_wbits[o * WSTRIDE + t]);
            nmiss++;
        }
    }
    g_fixf[m * OO + o] = (float)(2 * corr - CC * nmiss);
}

// ---------------------------------------------------------------------------
// Kernel 2: pack activations. Each thread packs 4 consecutive pixels via
// float4 loads per channel.
// ---------------------------------------------------------------------------
__global__ void pack_act_kernel(const float* __restrict__ act) {
    int tidg = blockIdx.x * blockDim.x + threadIdx.x;
    int p0   = tidg * 4;
    int n    = p0 / HW;
    int p    = p0 - n * HW;

    const float* base = act + (long)(n * CC) * HW + p;
    u64 w0 = 0, w1 = 0, w2 = 0, w3 = 0;
#pragma unroll
    for (int c = 0; c < CC; c++) {
        float4 v = *(const float4*)(base + (long)c * HW);
        w0 |= (u64)(v.x > 0.0f) << c;
        w1 |= (u64)(v.y > 0.0f) << c;
        w2 |= (u64)(v.z > 0.0f) << c;
        w3 |= (u64)(v.w > 0.0f) << c;
    }
    ulonglong2* dst = (ulonglong2*)(g_packed + p0);
    dst[0] = make_ulonglong2(w0, w1);
    dst[1] = make_ulonglong2(w2, w3);
}

// ---------------------------------------------------------------------------
// Kernel 3: binary conv, CSA-compressed popcount, border fix fused.
// Thread: 4 pixels, window 3x6 words. Block (28,4)=112; grid (28,32,2).
// Per (o,px): 9 XOR + 3 row-CSAs -> popc(s0..s2) + 2*popc(c0..c2).
// res = 576 - 2*acc via magic fma. Border classes corrected from smem table.
// ---------------------------------------------------------------------------
__global__ __launch_bounds__(112)
void bconv_kernel(float* __restrict__ out) {
    __shared__ __align__(16) u64 ws[OB * WSTRIDE];
    __shared__ float fix_s[16 * OB];

    int obase = blockIdx.z * OB;
    int t = threadIdx.y * 28 + threadIdx.x;
    for (int i = t; i < OB * WSTRIDE; i += 112)
        ws[i] = g_wbits[obase * WSTRIDE + i];
    for (int i = t; i < 16 * OB; i += 112)
        fix_s[i] = g_fixf[(i / OB) * OO + obase + (i % OB)];
    __syncthreads();

    int x0 = threadIdx.x * 4;
    int y  = blockIdx.x * 4 + threadIdx.y;
    int n  = blockIdx.y;

    const u64* pb = g_packed + (long)n * HW;

    // 3x6 window, zero for OOB (corrected via fix table)
    u64 a[3][6];
#pragma unroll
    for (int r = 0; r < 3; r++) {
        int yy = y - 1 + r;
        bool rv = (unsigned)yy < (unsigned)HH;
        const u64* row = pb + yy * WW;
#pragma unroll
        for (int c = 0; c < 6; c++) {
            int xx = x0 - 1 + c;
            bool v = rv && ((unsigned)xx < (unsigned)WW);
            a[r][c] = v ? row[xx] : 0ull;
        }
    }

    // Border class masks (per output pixel)
    int m_y = (y == 0 ? 1 : 0) | (y == 111 ? 2 : 0);
    int m0  = m_y | (x0 == 0 ? 4 : 0);
    int m3  = m_y | (x0 == 108 ? 8 : 0);
    bool anyb = (m0 | m3) != 0;

    const float MAGIC_SUB = 16777792.0f;  // 2^24 + 576

    float* ob = out + ((long)(n * OO + obase)) * HW + y * WW + x0;

#pragma unroll 2
    for (int o = 0; o < OB; o++) {
        const ulonglong2* wr2 = (const ulonglong2*)(ws + o * WSTRIDE);
        ulonglong2 wp0 = wr2[0], wp1 = wr2[1], wp2 = wr2[2], wp3 = wr2[3];
        u64 wv[9] = { wp0.x, wp0.y, wp1.x, wp1.y, wp2.x, wp2.y, wp3.x, wp3.y,
                      ws[o * WSTRIDE + 8] };

        float4 res;
#pragma unroll
        for (int px = 0; px < 4; px++) {
            u64 s0, s1, s2, c0, c1, c2;
            csa(s0, c0, a[0][px] ^ wv[0], a[0][px + 1] ^ wv[1], a[0][px + 2] ^ wv[2]);
            csa(s1, c1, a[1][px] ^ wv[3], a[1][px + 1] ^ wv[4], a[1][px + 2] ^ wv[5]);
            csa(s2, c2, a[2][px] ^ wv[6], a[2][px + 1] ^ wv[7], a[2][px + 2] ^ wv[8]);

            int sA = __popcll(s0) + __popcll(s1) + __popcll(s2);
            int sC = __popcll(c0) + __popcll(c1) + __popcll(c2);
            int acc = sA + 2 * sC;
            float v = fmaf(-2.0f, __int_as_float(0x4B000000 | acc), MAGIC_SUB);
            if (px == 0) res.x = v;
            else if (px == 1) res.y = v;
            else if (px == 2) res.z = v;
            else res.w = v;
        }

        if (anyb) {   // warp-uniform false for all interior warps
            res.x += fix_s[m0  * OB + o];
            res.y += fix_s[m_y * OB + o];
            res.z += fix_s[m_y * OB + o];
            res.w += fix_s[m3  * OB + o];
        }

        *(float4*)(ob + (long)o * HW) = res;
    }
}

// ---------------------------------------------------------------------------
extern "C" void kernel_launch(void* const* d_in, const int* in_sizes, int n_in,
                              void* d_out, int out_size) {
    const float* act = (const float*)d_in[0];   // [32,64,112,112]
    const float* w   = (const float*)d_in[1];   // [64*64*9, 1]
    float* out       = (float*)d_out;           // [32,64,112,112]

    pack_weights_kernel<<<72, 256>>>(w);
    pack_fix_kernel<<<16, OO>>>();

    pack_act_kernel<<<(NN * HW / 4) / 128, 128>>>(act);

    dim3 block(28, 4);
    dim3 grid(HH / 4, NN, 2);
    bconv_kernel<<<grid, block>>>(out);
}

// round 7
// speedup vs baseline: 1.3982x; 1.0170x over previous
#include <cuda_runtime.h>
#include <cstdint>

#define NN   32
#define CC   64
#define HH   112
#define WW   112
#define HW   (HH*WW)        // 12544
#define OO   64
#define TAPS 9
#define WSTRIDE 10          // padded weight row (16B-aligned rows: 80 bytes)
#define OB   32             // output channels per block (o-split)

typedef unsigned long long u64;

// Static device scratch (no allocation)
__device__ __align__(16) u64 g_packed[NN * HW];        // bit c = (A[n][c][y][x] > 0)
__device__ __align__(16) u64 g_wbits[OO * WSTRIDE];    // padded rows of 10
__device__ float             g_fixf[16 * OO];          // per edge-class per o correction (float)

// Full adder (carry-save)
__device__ __forceinline__ void csa(u64& s, u64& c, u64 x, u64 y, u64 z) {
    u64 u = x ^ y;
    s = u ^ z;
    c = (x & y) | (u & z);
}

// ---------------------------------------------------------------------------
// Kernel 1: pack weights. One warp per (o,t); lane covers channels lane, lane+32.
// ---------------------------------------------------------------------------
__global__ void pack_weights_kernel(const float* __restrict__ w) {
    int wid  = blockIdx.x * (blockDim.x >> 5) + (threadIdx.x >> 5);
    int lane = threadIdx.x & 31;
    if (wid >= OO * TAPS) return;
    int o = wid / TAPS, t = wid % TAPS;
    float v0 = w[(o * CC + lane) * TAPS + t];
    float v1 = w[(o * CC + lane + 32) * TAPS + t];
    unsigned b0 = __ballot_sync(0xFFFFFFFFu, v0 > 0.0f);
    unsigned b1 = __ballot_sync(0xFFFFFFFFu, v1 > 0.0f);
    if (lane == 0)
        g_wbits[o * WSTRIDE + t] = (u64)b0 | ((u64)b1 << 32);
}

// ---------------------------------------------------------------------------
// Kernel 1b: border fix table (float). blockIdx.x = edge class mask m
// (bit0: y==0, bit1: y==111, bit2: x==0, bit3: x==111), threadIdx.x = o.
// fix = 2*sum_{invalid taps} popc(w) - 64*n_missing ;  class 0 -> 0.0f
// ---------------------------------------------------------------------------
__global__ void pack_fix_kernel() {
    int m = blockIdx.x;     // 0..15
    int o = threadIdx.x;    // 0..63
    bool T = m & 1, B = m & 2, L = m & 4, R = m & 8;
    int corr = 0, nmiss = 0;
#pragma unroll
    for (int t = 0; t < 9; t++) {
        int r = t / 3, c = t % 3;
        bool inv = (T && r == 0) || (B && r == 2) || (L && c == 0) || (R && c == 2);
        if (inv) {
            corr += __popcll(g_wbits[o * WSTRIDE + t]);
            nmiss++;
        }
    }
    g_fixf[m * OO + o] = (float)(2 * corr - CC * nmiss);
}

// ---------------------------------------------------------------------------
// Kernel 2: pack activations. Each thread packs 4 consecutive pixels via
// float4 loads per channel.
// ---------------------------------------------------------------------------
__global__ void pack_act_kernel(const float* __restrict__ act) {
    int tidg = blockIdx.x * blockDim.x + threadIdx.x;
    int p0   = tidg * 4;
    int n    = p0 / HW;
    int p    = p0 - n * HW;

    const float* base = act + (long)(n * CC) * HW + p;
    u64 w0 = 0, w1 = 0, w2 = 0, w3 = 0;
#pragma unroll
    for (int c = 0; c < CC; c++) {
        float4 v = *(const float4*)(base + (long)c * HW);
        w0 |= (u64)(v.x > 0.0f) << c;
        w1 |= (u64)(v.y > 0.0f) << c;
        w2 |= (u64)(v.z > 0.0f) << c;
        w3 |= (u64)(v.w > 0.0f) << c;
    }
    ulonglong2* dst = (ulonglong2*)(g_packed + p0);
    dst[0] = make_ulonglong2(w0, w1);
    dst[1] = make_ulonglong2(w2, w3);
}

// ---------------------------------------------------------------------------
// Kernel 3: binary conv, 4-CSA compressed popcount (r5 core), fused border.
// Thread: 4 pixels, window 3x6 words. Block (28,4)=112; grid (28,32,2).
// Per (o,px): 9 XOR + 4 CSA -> popc(s0)+popc(s1)+popc(s2)+2popc(s3)+4popc(c3).
// res = 576 - 2*acc via magic fma. Border classes corrected from smem table.
// ---------------------------------------------------------------------------
__global__ __launch_bounds__(112)
void bconv_kernel(float* __restrict__ out) {
    __shared__ __align__(16) u64 ws[OB * WSTRIDE];
    __shared__ float fix_s[16 * OB];

    int obase = blockIdx.z * OB;
    int t = threadIdx.y * 28 + threadIdx.x;
    for (int i = t; i < OB * WSTRIDE; i += 112)
        ws[i] = g_wbits[obase * WSTRIDE + i];
    for (int i = t; i < 16 * OB; i += 112)
        fix_s[i] = g_fixf[(i / OB) * OO + obase + (i % OB)];
    __syncthreads();

    int x0 = threadIdx.x * 4;
    int y  = blockIdx.x * 4 + threadIdx.y;
    int n  = blockIdx.y;

    const u64* pb = g_packed + (long)n * HW;

    // 3x6 window, zero for OOB (corrected via fix table)
    u64 a[3][6];
#pragma unroll
    for (int r = 0; r < 3; r++) {
        int yy = y - 1 + r;
        bool rv = (unsigned)yy < (unsigned)HH;
        const u64* row = pb + yy * WW;
#pragma unroll
        for (int c = 0; c < 6; c++) {
            int xx = x0 - 1 + c;
            bool v = rv && ((unsigned)xx < (unsigned)WW);
            a[r][c] = v ? row[xx] : 0ull;
        }
    }

    // Border class masks (per output pixel)
    int m_y = (y == 0 ? 1 : 0) | (y == 111 ? 2 : 0);
    int m0  = m_y | (x0 == 0 ? 4 : 0);
    int m3  = m_y | (x0 == 108 ? 8 : 0);
    bool anyb = (m0 | m3) != 0;

    const float MAGIC_SUB = 16777792.0f;  // 2^24 + 576

    float* ob = out + ((long)(n * OO + obase)) * HW + y * WW + x0;

#pragma unroll 2
    for (int o = 0; o < OB; o++) {
        const ulonglong2* wr2 = (const ulonglong2*)(ws + o * WSTRIDE);
        ulonglong2 wp0 = wr2[0], wp1 = wr2[1], wp2 = wr2[2], wp3 = wr2[3];
        u64 wv[9] = { wp0.x, wp0.y, wp1.x, wp1.y, wp2.x, wp2.y, wp3.x, wp3.y,
                      ws[o * WSTRIDE + 8] };

        float4 res;
#pragma unroll
        for (int px = 0; px < 4; px++) {
            u64 s0, s1, s2, s3, c0, c1, c2, c3;
            csa(s0, c0, a[0][px] ^ wv[0], a[0][px + 1] ^ wv[1], a[0][px + 2] ^ wv[2]);
            csa(s1, c1, a[1][px] ^ wv[3], a[1][px + 1] ^ wv[4], a[1][px + 2] ^ wv[5]);
            csa(s2, c2, a[2][px] ^ wv[6], a[2][px + 1] ^ wv[7], a[2][px + 2] ^ wv[8]);
            csa(s3, c3, c0, c1, c2);

            int acc = __popcll(s0) + __popcll(s1) + __popcll(s2)
                    + 2 * __popcll(s3) + 4 * __popcll(c3);
            float v = fmaf(-2.0f, __int_as_float(0x4B000000 | acc), MAGIC_SUB);
            if (px == 0) res.x = v;
            else if (px == 1) res.y = v;
            else if (px == 2) res.z = v;
            else res.w = v;
        }

        if (anyb) {   // warp-uniform false for all interior warps
            res.x += fix_s[m0  * OB + o];
            res.y += fix_s[m_y * OB + o];
            res.z += fix_s[m_y * OB + o];
            res.w += fix_s[m3  * OB + o];
        }

        *(float4*)(ob + (long)o * HW) = res;
    }
}

// ---------------------------------------------------------------------------
extern "C" void kernel_launch(void* const* d_in, const int* in_sizes, int n_in,
                              void* d_out, int out_size) {
    const float* act = (const float*)d_in[0];   // [32,64,112,112]
    const float* w   = (const float*)d_in[1];   // [64*64*9, 1]
    float* out       = (float*)d_out;           // [32,64,112,112]

    pack_weights_kernel<<<72, 256>>>(w);
    pack_fix_kernel<<<16, OO>>>();

    pack_act_kernel<<<(NN * HW / 4) / 128, 128>>>(act);

    dim3 block(28, 4);
    dim3 grid(HH / 4, NN, 2);
    bconv_kernel<<<grid, block>>>(out);
}